// round 8
// baseline (speedup 1.0000x reference)
#include <cuda_runtime.h>
#include <cuda_fp16.h>
#include <cstdint>
#include <math.h>

static constexpr int Bz  = 4096;
static constexpr int Ls  = 10;
static constexpr int IND = 8;
static constexpr int Hd  = 512;
static constexpr int Gd  = 1536;   // 3*Hd
static constexpr int KW  = 1024;   // weight split row: [hi 512 | lo 512] fp16

// ---------------- scratch (offsets in float units) ----------------
static constexpr size_t OFF_XG_DEC  = 0;                                     // Bz*Gd f32
static constexpr size_t OFF_ENC_OUT = OFF_XG_DEC  + (size_t)Bz*Gd;           // Ls*Bz*Hd f32
static constexpr size_t OFF_ENC1    = OFF_ENC_OUT + (size_t)Ls*Bz*Hd;        // Ls*Bz*Hd fp16
static constexpr size_t OFF_ENC_W3  = OFF_ENC1    + (size_t)Ls*Bz*Hd/2;      // Ls*Bz*Hd f32
static constexpr size_t OFF_H_ALL   = OFF_ENC_W3  + (size_t)Ls*Bz*Hd;        // Ls*Bz*Hd f32
static constexpr size_t OFF_A_ALL   = OFF_H_ALL   + (size_t)Ls*Bz*Hd;        // Ls*Bz*Hd f32
static constexpr size_t OFF_H1_ALL  = OFF_A_ALL   + (size_t)Ls*Bz*Hd;        // Ls*Bz*Hd fp16
static constexpr size_t OFF_DEC1    = OFF_H1_ALL  + (size_t)Ls*Bz*Hd/2;      // Bz*Hd fp16
static constexpr size_t OFF_WHHE2   = OFF_DEC1    + (size_t)Bz*Hd/2;         // Gd*KW fp16
static constexpr size_t OFF_WHHD2   = OFF_WHHE2   + (size_t)Gd*KW/2;
static constexpr size_t OFF_WIHD2   = OFF_WHHD2   + (size_t)Gd*KW/2;
static constexpr size_t OFF_W32     = OFF_WIHD2   + (size_t)Gd*KW/2;         // Hd*KW fp16
static constexpr size_t OFF_W42     = OFF_W32     + (size_t)Hd*KW/2;
static constexpr size_t OFF_CW      = OFF_W42     + (size_t)Hd*KW/2;         // Gd*IND f32
static constexpr size_t OFF_CB      = OFF_CW      + (size_t)Gd*IND;          // Gd f32
static constexpr size_t SCRATCH_TOTAL = OFF_CB + Gd;

__device__ __align__(1024) float g_scratch[SCRATCH_TOTAL];

// ---------------- math helpers ----------------
__device__ __forceinline__ float sigm_f(float x) { return 1.0f / (1.0f + __expf(-x)); }
__device__ __forceinline__ float tanh_f(float x) {
    float ax = fabsf(x);
    float t  = __expf(-2.0f * ax);
    float r  = __fdividef(1.0f - t, 1.0f + t);
    return copysignf(r, x);
}

// ---------------- PTX helpers ----------------
__device__ __forceinline__ uint32_t smem_u32(const void* p) {
    uint32_t a;
    asm("{ .reg .u64 t; cvta.to.shared.u64 t, %1; cvt.u32.u64 %0, t; }" : "=r"(a) : "l"(p));
    return a;
}
__device__ __forceinline__ void cp16(uint32_t s, const void* g) {
    asm volatile("cp.async.cg.shared.global [%0], [%1], 16;" :: "r"(s), "l"(g) : "memory");
}
__device__ __forceinline__ void ldm_x4(uint32_t& r0, uint32_t& r1, uint32_t& r2, uint32_t& r3,
                                       uint32_t addr) {
    asm volatile("ldmatrix.sync.aligned.m8n8.x4.shared.b16 {%0,%1,%2,%3}, [%4];"
                 : "=r"(r0), "=r"(r1), "=r"(r2), "=r"(r3) : "r"(addr));
}
__device__ __forceinline__ void mma16816(float* c, const uint32_t* a, uint32_t b0, uint32_t b1) {
    asm volatile("mma.sync.aligned.m16n8k16.row.col.f32.f16.f16.f32 "
                 "{%0,%1,%2,%3}, {%4,%5,%6,%7}, {%8,%9}, {%0,%1,%2,%3};"
                 : "+f"(c[0]), "+f"(c[1]), "+f"(c[2]), "+f"(c[3])
                 : "r"(a[0]), "r"(a[1]), "r"(a[2]), "r"(a[3]), "r"(b0), "r"(b1));
}

static constexpr int AB_STRIDE = 10240;   // 128 rows * 80 B
static constexpr int BB_STRIDE = 20480;   // 256 rows * 80 B

// ---------------- standalone fp16x2 GEMM: C[M,N] = A @ (Whi+Wlo)^T (+bias) ----------------
__global__ void __launch_bounds__(256, 2) k_gemm_mma(
    const __half* __restrict__ A1, const __half* __restrict__ W2,
    const float* __restrict__ bias, float* __restrict__ C, int N)
{
    __shared__ __half As[2][128][40];
    __shared__ __half Bs[2][256][40];
    const int tid  = threadIdx.x;
    const int wid  = tid >> 5, lane = tid & 31;
    const int wm   = wid & 3;
    const int wn   = wid >> 2;
    const size_t bm = (size_t)blockIdx.x * 128;
    const size_t bn = (size_t)blockIdx.y * 128;

    const uint32_t sA = smem_u32(As);
    const uint32_t sB = smem_u32(Bs);

    float acc[2][8][4];
#pragma unroll
    for (int i = 0; i < 2; i++)
#pragma unroll
        for (int j = 0; j < 8; j++)
#pragma unroll
            for (int q = 0; q < 4; q++) acc[i][j][q] = 0.0f;

    const int lrow = tid >> 2;
    const int lcol = (tid & 3) << 4;
    const char* aG = (const char*)A1 + (bm + lrow) * 1024 + lcol;
    const char* bG = (const char*)W2 + (bn + lrow) * 2048 + lcol;
    const uint32_t dA = sA + lrow * 80 + lcol;
    const uint32_t dB = sB + lrow * 80 + lcol;

#define LOAD_TILE(kt, buf)                                                     \
    {                                                                          \
        int ko_ = (kt) * 64;                                                   \
        cp16(dA + (buf) * AB_STRIDE,            aG + ko_);                     \
        cp16(dA + (buf) * AB_STRIDE + 64 * 80,  aG + 64 * 1024 + ko_);         \
        cp16(dB + (buf) * BB_STRIDE,            bG + ko_);                     \
        cp16(dB + (buf) * BB_STRIDE + 64 * 80,  bG + 64 * 2048 + ko_);         \
        cp16(dB + (buf) * BB_STRIDE + 128 * 80, bG + 1024 + ko_);              \
        cp16(dB + (buf) * BB_STRIDE + 192 * 80, bG + 64 * 2048 + 1024 + ko_);  \
        asm volatile("cp.async.commit_group;" ::: "memory");                   \
    }

    LOAD_TILE(0, 0);

    const uint32_t mA0 = sA + (wm * 32 + (lane & 15)) * 80 + ((lane >> 4) << 4);
    const uint32_t mB0 = sB + (wn * 64 + (lane & 15)) * 80 + ((lane >> 4) << 4);

    for (int kt = 0; kt < 16; kt++) {
        int buf = kt & 1;
        if (kt < 15) {
            LOAD_TILE(kt + 1, buf ^ 1);
            asm volatile("cp.async.wait_group 1;" ::: "memory");
        } else {
            asm volatile("cp.async.wait_group 0;" ::: "memory");
        }
        __syncthreads();

#pragma unroll
        for (int ks = 0; ks < 2; ks++) {
            uint32_t a[2][4], b[4][4];
#pragma unroll
            for (int mf = 0; mf < 2; mf++)
                ldm_x4(a[mf][0], a[mf][1], a[mf][2], a[mf][3],
                       mA0 + buf * AB_STRIDE + mf * 16 * 80 + ks * 32);
#pragma unroll
            for (int nb = 0; nb < 4; nb++)
                ldm_x4(b[nb][0], b[nb][1], b[nb][2], b[nb][3],
                       mB0 + buf * BB_STRIDE + nb * 16 * 80 + ks * 32);
#pragma unroll
            for (int mf = 0; mf < 2; mf++)
#pragma unroll
                for (int nb = 0; nb < 4; nb++) {
                    mma16816(acc[mf][2 * nb + 0], a[mf], b[nb][0], b[nb][2]);
                    mma16816(acc[mf][2 * nb + 1], a[mf], b[nb][1], b[nb][3]);
                }
#pragma unroll
            for (int nb = 0; nb < 4; nb++)
                ldm_x4(b[nb][0], b[nb][1], b[nb][2], b[nb][3],
                       mB0 + buf * BB_STRIDE + 128 * 80 + nb * 16 * 80 + ks * 32);
#pragma unroll
            for (int mf = 0; mf < 2; mf++)
#pragma unroll
                for (int nb = 0; nb < 4; nb++) {
                    mma16816(acc[mf][2 * nb + 0], a[mf], b[nb][0], b[nb][2]);
                    mma16816(acc[mf][2 * nb + 1], a[mf], b[nb][1], b[nb][3]);
                }
        }
        __syncthreads();
    }
#undef LOAD_TILE

#pragma unroll
    for (int mf = 0; mf < 2; mf++) {
#pragma unroll
        for (int nf = 0; nf < 8; nf++) {
            size_t r0 = bm + wm * 32 + mf * 16 + (lane >> 2);
            int    c0 = (int)bn + wn * 64 + nf * 8 + (lane & 3) * 2;
            float bv0 = 0.f, bv1 = 0.f;
            if (bias) { bv0 = bias[c0]; bv1 = bias[c0 + 1]; }
            float2 o0 = make_float2(acc[mf][nf][0] + bv0, acc[mf][nf][1] + bv1);
            float2 o1 = make_float2(acc[mf][nf][2] + bv0, acc[mf][nf][3] + bv1);
            *reinterpret_cast<float2*>(&C[r0 * (size_t)N + c0])       = o0;
            *reinterpret_cast<float2*>(&C[(r0 + 8) * (size_t)N + c0]) = o1;
        }
    }
}

// ---------------- fused GRU step: GEMM over 3 gates + gate math in epilogue ----------------
// Each CTA: 128 batch rows x 128 j-cols. Gate g uses W rows [g*512 + jn*128 .. +128).
// r/z accumulators (+bhh bias) stash in smem (same-thread producer/consumer).
// Epilogue: xg from XG buffer (decoder) or inline items.cw dots (encoder).
static constexpr int FUSED_SMEM = 196608;   // 20K As + 40K Bs + 2 x 66K C-stash

__global__ void __launch_bounds__(256, 1) k_gru_fused(
    const __half* __restrict__ A1, const __half* __restrict__ W2,
    const float* __restrict__ bhh,
    const float* __restrict__ xg,                      // decoder mode if non-null
    const float* __restrict__ items, int t,
    const float* __restrict__ cw, const float* __restrict__ cb,
    const float* __restrict__ hprev,
    float* __restrict__ hout, __half* __restrict__ h1)
{
    extern __shared__ char smem[];
    const uint32_t sA = smem_u32(smem);
    const uint32_t sB = sA + 20480;
    float* Cr = (float*)(smem + 61440);
    float* Cz = (float*)(smem + 61440 + 67584);

    const int tid = threadIdx.x;
    const int wid = tid >> 5, lane = tid & 31;
    const int wm = wid & 3, wn = wid >> 2;
    const size_t bm = (size_t)blockIdx.x * 128;
    const int jn = blockIdx.y;                          // j-tile 0..3

    const int lrow = tid >> 2;
    const int lcol = (tid & 3) << 4;
    const char* aG = (const char*)A1 + (bm + lrow) * 1024 + lcol;
    const uint32_t dA = sA + lrow * 80 + lcol;
    const uint32_t dB = sB + lrow * 80 + lcol;
    const uint32_t mA0 = sA + (wm * 32 + (lane & 15)) * 80 + ((lane >> 4) << 4);
    const uint32_t mB0 = sB + (wn * 64 + (lane & 15)) * 80 + ((lane >> 4) << 4);

    float acc[2][8][4];

    for (int g = 0; g < 3; g++) {
        const char* bG = (const char*)W2 + ((size_t)(g * 512 + jn * 128) + lrow) * 2048 + lcol;
#pragma unroll
        for (int i = 0; i < 2; i++)
#pragma unroll
            for (int j = 0; j < 8; j++)
#pragma unroll
                for (int q = 0; q < 4; q++) acc[i][j][q] = 0.0f;

#define FLOAD(kt, buf)                                                         \
    {                                                                          \
        int ko_ = (kt) * 64;                                                   \
        cp16(dA + (buf) * AB_STRIDE,            aG + ko_);                     \
        cp16(dA + (buf) * AB_STRIDE + 64 * 80,  aG + 64 * 1024 + ko_);         \
        cp16(dB + (buf) * BB_STRIDE,            bG + ko_);                     \
        cp16(dB + (buf) * BB_STRIDE + 64 * 80,  bG + 64 * 2048 + ko_);         \
        cp16(dB + (buf) * BB_STRIDE + 128 * 80, bG + 1024 + ko_);              \
        cp16(dB + (buf) * BB_STRIDE + 192 * 80, bG + 64 * 2048 + 1024 + ko_);  \
        asm volatile("cp.async.commit_group;" ::: "memory");                   \
    }

        FLOAD(0, 0);
        for (int kt = 0; kt < 16; kt++) {
            int buf = kt & 1;
            if (kt < 15) {
                FLOAD(kt + 1, buf ^ 1);
                asm volatile("cp.async.wait_group 1;" ::: "memory");
            } else {
                asm volatile("cp.async.wait_group 0;" ::: "memory");
            }
            __syncthreads();

#pragma unroll
            for (int ks = 0; ks < 2; ks++) {
                uint32_t a[2][4], b[4][4];
#pragma unroll
                for (int mf = 0; mf < 2; mf++)
                    ldm_x4(a[mf][0], a[mf][1], a[mf][2], a[mf][3],
                           mA0 + buf * AB_STRIDE + mf * 16 * 80 + ks * 32);
#pragma unroll
                for (int nb = 0; nb < 4; nb++)
                    ldm_x4(b[nb][0], b[nb][1], b[nb][2], b[nb][3],
                           mB0 + buf * BB_STRIDE + nb * 16 * 80 + ks * 32);
#pragma unroll
                for (int mf = 0; mf < 2; mf++)
#pragma unroll
                    for (int nb = 0; nb < 4; nb++) {
                        mma16816(acc[mf][2 * nb + 0], a[mf], b[nb][0], b[nb][2]);
                        mma16816(acc[mf][2 * nb + 1], a[mf], b[nb][1], b[nb][3]);
                    }
#pragma unroll
                for (int nb = 0; nb < 4; nb++)
                    ldm_x4(b[nb][0], b[nb][1], b[nb][2], b[nb][3],
                           mB0 + buf * BB_STRIDE + 128 * 80 + nb * 16 * 80 + ks * 32);
#pragma unroll
                for (int mf = 0; mf < 2; mf++)
#pragma unroll
                    for (int nb = 0; nb < 4; nb++) {
                        mma16816(acc[mf][2 * nb + 0], a[mf], b[nb][0], b[nb][2]);
                        mma16816(acc[mf][2 * nb + 1], a[mf], b[nb][1], b[nb][3]);
                    }
            }
            __syncthreads();
        }
#undef FLOAD

        if (g < 2) {
            float* Cd = g ? Cz : Cr;
            const float* bb = bhh + g * 512 + jn * 128;
#pragma unroll
            for (int mf = 0; mf < 2; mf++)
#pragma unroll
                for (int nf = 0; nf < 8; nf++) {
                    int lr = wm * 32 + mf * 16 + (lane >> 2);
                    int lc = wn * 64 + nf * 8 + (lane & 3) * 2;
                    float bv0 = bb[lc], bv1 = bb[lc + 1];
                    Cd[lr * 132 + lc]           = acc[mf][nf][0] + bv0;
                    Cd[lr * 132 + lc + 1]       = acc[mf][nf][1] + bv1;
                    Cd[(lr + 8) * 132 + lc]     = acc[mf][nf][2] + bv0;
                    Cd[(lr + 8) * 132 + lc + 1] = acc[mf][nf][3] + bv1;
                }
        }
        __syncthreads();
    }

    // fused GRU epilogue: acc holds n-gate pre-activation (no bias yet)
    const float* bbn = bhh + 1024 + jn * 128;
#pragma unroll
    for (int mf = 0; mf < 2; mf++)
#pragma unroll
        for (int nf = 0; nf < 8; nf++) {
            int lr = wm * 32 + mf * 16 + (lane >> 2);
            int lc = wn * 64 + nf * 8 + (lane & 3) * 2;
            float bvn0 = bbn[lc], bvn1 = bbn[lc + 1];
#pragma unroll
            for (int dr = 0; dr < 2; dr++) {
                int row = lr + dr * 8;
                size_t b = bm + row;
                int jj = jn * 128 + lc;
                float hgn0 = acc[mf][nf][dr * 2 + 0] + bvn0;
                float hgn1 = acc[mf][nf][dr * 2 + 1] + bvn1;
                float hgr0 = Cr[row * 132 + lc], hgr1 = Cr[row * 132 + lc + 1];
                float hgz0 = Cz[row * 132 + lc], hgz1 = Cz[row * 132 + lc + 1];
                float xr0, xz0, xn0, xr1, xz1, xn1;
                if (xg) {
                    const float* x = xg + b * Gd;
                    float2 v;
                    v = *reinterpret_cast<const float2*>(x + jj);        xr0 = v.x; xr1 = v.y;
                    v = *reinterpret_cast<const float2*>(x + 512 + jj);  xz0 = v.x; xz1 = v.y;
                    v = *reinterpret_cast<const float2*>(x + 1024 + jj); xn0 = v.x; xn1 = v.y;
                } else {
                    const float4* it = reinterpret_cast<const float4*>(items + (b * Ls + t) * IND);
                    float4 i0 = it[0], i1 = it[1];
                    auto xdot = [&](int gg) {
                        const float4* w = reinterpret_cast<const float4*>(cw + (size_t)gg * IND);
                        float4 w0 = w[0], w1 = w[1];
                        return cb[gg]
                            + i0.x * w0.x + i0.y * w0.y + i0.z * w0.z + i0.w * w0.w
                            + i1.x * w1.x + i1.y * w1.y + i1.z * w1.z + i1.w * w1.w;
                    };
                    xr0 = xdot(jj);          xr1 = xdot(jj + 1);
                    xz0 = xdot(512 + jj);    xz1 = xdot(512 + jj + 1);
                    xn0 = xdot(1024 + jj);   xn1 = xdot(1024 + jj + 1);
                }
                size_t o = b * Hd + jj;
                float2 hp = *reinterpret_cast<const float2*>(&hprev[o]);
                float r0 = sigm_f(xr0 + hgr0), r1 = sigm_f(xr1 + hgr1);
                float z0 = sigm_f(xz0 + hgz0), z1 = sigm_f(xz1 + hgz1);
                float n0 = tanh_f(xn0 + r0 * hgn0), n1 = tanh_f(xn1 + r1 * hgn1);
                float v0 = n0 + z0 * (hp.x - n0), v1 = n1 + z1 * (hp.y - n1);
                *reinterpret_cast<float2*>(&hout[o]) = make_float2(v0, v1);
                *reinterpret_cast<__half2*>(&h1[o])  = __floats2half2_rn(v0, v1);
            }
        }
}

// ---------------- weight split: f32[n,512] -> fp16[n,1024] hi|lo ----------------
__global__ void k_split_w(const float* __restrict__ in, __half* __restrict__ out)
{
    size_t idx = (size_t)blockIdx.x * blockDim.x + threadIdx.x;
    size_t r = idx >> 9; int j = (int)(idx & 511);
    float v = in[idx];
    __half hi = __float2half(v);
    float lo = v - __half2float(hi);
    out[r * KW + j]       = hi;
    out[r * KW + 512 + j] = __float2half(lo);
}

// ---------------- cast: f32 -> fp16 ----------------
__global__ void k_cast(const float* __restrict__ in, __half* __restrict__ out)
{
    size_t idx = (size_t)blockIdx.x * blockDim.x + threadIdx.x;
    out[idx] = __float2half(in[idx]);
}

// ---------------- combine: cw = enc_wih @ emb_w, cb = enc_wih@emb_b + enc_bih ----------------
__global__ void k_combine(const float* __restrict__ enc_wih, const float* __restrict__ emb_w,
                          const float* __restrict__ emb_b,  const float* __restrict__ enc_bih,
                          float* __restrict__ cw, float* __restrict__ cb)
{
    int g = blockIdx.x, tid = threadIdx.x;
    float p[IND + 1];
#pragma unroll
    for (int i = 0; i <= IND; i++) p[i] = 0.0f;
    const float* wr = enc_wih + (size_t)g * Hd;
    for (int k = tid; k < Hd; k += 128) {
        float wv = wr[k];
#pragma unroll
        for (int i = 0; i < IND; i++) p[i] += wv * emb_w[(size_t)k * IND + i];
        p[IND] += wv * emb_b[k];
    }
#pragma unroll
    for (int i = 0; i <= IND; i++)
        for (int o = 16; o; o >>= 1) p[i] += __shfl_xor_sync(0xffffffffu, p[i], o);
    __shared__ float red[IND + 1][4];
    int wid = tid >> 5, lane = tid & 31;
    if (!lane)
#pragma unroll
        for (int i = 0; i <= IND; i++) red[i][wid] = p[i];
    __syncthreads();
    if (tid <= IND) {
        float s = red[tid][0] + red[tid][1] + red[tid][2] + red[tid][3];
        if (tid < IND) cw[(size_t)g * IND + tid] = s;
        else           cb[g] = s + enc_bih[g];
    }
}

// ---------------- encoder t=0 gate (hg = bias only) ----------------
__global__ void k_gate_enc0(const float* __restrict__ items,
                            const float* __restrict__ cw, const float* __restrict__ cb,
                            const float* __restrict__ bhh,
                            float* __restrict__ hout, __half* __restrict__ h1)
{
    int idx = blockIdx.x * blockDim.x + threadIdx.x;
    int b = idx >> 9, j = idx & 511;
    const float4* it = reinterpret_cast<const float4*>(items + (size_t)b * Ls * IND);
    float4 i0 = it[0], i1 = it[1];
    auto xdot = [&](int g) {
        const float4* w = reinterpret_cast<const float4*>(cw + (size_t)g * IND);
        float4 w0 = w[0], w1 = w[1];
        return cb[g]
            + i0.x * w0.x + i0.y * w0.y + i0.z * w0.z + i0.w * w0.w
            + i1.x * w1.x + i1.y * w1.y + i1.z * w1.z + i1.w * w1.w;
    };
    float r = sigm_f(xdot(j) + bhh[j]);
    float z = sigm_f(xdot(Hd + j) + bhh[Hd + j]);
    float n = tanh_f(xdot(2 * Hd + j) + r * bhh[2 * Hd + j]);
    float v = n - z * n;    // hp = 0
    hout[idx] = v;
    h1[idx] = __float2half(v);
}

// ---------------- batched out_seq over all (t, l): one block per b ----------------
__global__ void __launch_bounds__(256) k_seq_all(
    const float* __restrict__ encw3, const float* __restrict__ A_all,
    const float* __restrict__ v2, float* __restrict__ out)
{
    int b = blockIdx.x, tid = threadIdx.x;
    int wid = tid >> 5, lane = tid & 31;
    __shared__ float Ash[Ls][Hd];
    __shared__ float v2s[Hd];
    __shared__ float red[8][Ls];
    for (int i = tid; i < Hd; i += 256) v2s[i] = v2[i];
    for (int t = 0; t < Ls; t++)
        for (int i = tid; i < Hd; i += 256)
            Ash[t][i] = A_all[((size_t)t * Bz + b) * Hd + i];
    __syncthreads();

    for (int l = 0; l < Ls; l++) {
        const float* e = encw3 + ((size_t)l * Bz + b) * Hd;
        float s[Ls];
#pragma unroll
        for (int t = 0; t < Ls; t++) s[t] = 0.0f;
#pragma unroll
        for (int it = 0; it < 2; it++) {
            int k = tid + it * 256;
            float ek = e[k], vk = v2s[k];
#pragma unroll
            for (int t = 0; t < Ls; t++) s[t] += vk * tanh_f(ek + Ash[t][k]);
        }
#pragma unroll
        for (int t = 0; t < Ls; t++)
            for (int o = 16; o; o >>= 1) s[t] += __shfl_xor_sync(0xffffffffu, s[t], o);
        if (!lane)
#pragma unroll
            for (int t = 0; t < Ls; t++) red[wid][t] = s[t];
        __syncthreads();
        if (tid < Ls) {
            float tot = 0.0f;
#pragma unroll
            for (int w = 0; w < 8; w++) tot += red[w][tid];
            out[((size_t)b * Ls + tid) * Ls + l] = tot;
        }
        __syncthreads();
    }
}

// ---------------- batched out_ori: one warp per (t, b) ----------------
__global__ void k_ori_all(const float* __restrict__ H_all, const float* __restrict__ wori,
                          const float* __restrict__ bori, float* __restrict__ out)
{
    int gw   = (blockIdx.x * blockDim.x + threadIdx.x) >> 5;  // t*Bz + b
    int lane = threadIdx.x & 31;
    int t = gw >> 12, b = gw & 4095;
    float s[6] = {0, 0, 0, 0, 0, 0};
    const float* hb = H_all + ((size_t)t * Bz + b) * Hd;
    for (int k = lane; k < Hd; k += 32) {
        float hv = hb[k];
#pragma unroll
        for (int j = 0; j < 6; j++) s[j] += hv * wori[(size_t)j * Gd + Hd + k];
    }
#pragma unroll
    for (int j = 0; j < 6; j++)
        for (int o = 16; o; o >>= 1) s[j] += __shfl_xor_sync(0xffffffffu, s[j], o);
    if (!lane)
#pragma unroll
        for (int j = 0; j < 6; j++)
            out[((size_t)b * Ls + t) * 6 + j] = s[j] + bori[j];
}

// ---------------- launch ----------------
extern "C" void kernel_launch(void* const* d_in, const int* in_sizes, int n_in,
                              void* d_out, int out_size)
{
    const float* items    = (const float*)d_in[0];
    const float* dec_in   = (const float*)d_in[1];
    const float* emb_w    = (const float*)d_in[2];
    const float* emb_b    = (const float*)d_in[3];
    const float* enc_wih  = (const float*)d_in[4];
    const float* enc_whh  = (const float*)d_in[5];
    const float* enc_bih  = (const float*)d_in[6];
    const float* enc_bhh  = (const float*)d_in[7];
    const float* dec_wih  = (const float*)d_in[8];
    const float* dec_whh  = (const float*)d_in[9];
    const float* dec_bih  = (const float*)d_in[10];
    const float* dec_bhh  = (const float*)d_in[11];
    const float* w3       = (const float*)d_in[14];
    const float* w4       = (const float*)d_in[15];
    const float* v2       = (const float*)d_in[20];
    const float* wori     = (const float*)d_in[23];
    const float* bori     = (const float*)d_in[24];

    float* out_seq = (float*)d_out;                        // (Bz, Ls, Ls)
    float* out_ori = (float*)d_out + (size_t)Bz * Ls * Ls; // (Bz, Ls, 6)

    float* S = nullptr;
    cudaGetSymbolAddress((void**)&S, g_scratch);
    float* XG_DEC  = S + OFF_XG_DEC;
    float* ENC_OUT = S + OFF_ENC_OUT;
    float* ENC_W3  = S + OFF_ENC_W3;
    float* H_ALL   = S + OFF_H_ALL;
    float* A_ALL   = S + OFF_A_ALL;
    float* CW      = S + OFF_CW;
    float* CB      = S + OFF_CB;
    __half* ENC1   = (__half*)(S + OFF_ENC1);
    __half* H1_ALL = (__half*)(S + OFF_H1_ALL);
    __half* DEC1   = (__half*)(S + OFF_DEC1);
    __half* WHHE2  = (__half*)(S + OFF_WHHE2);
    __half* WHHD2  = (__half*)(S + OFF_WHHD2);
    __half* WIHD2  = (__half*)(S + OFF_WIHD2);
    __half* W32    = (__half*)(S + OFF_W32);
    __half* W42    = (__half*)(S + OFF_W42);

    static bool attr_set = false;
    if (!attr_set) {
        cudaFuncSetAttribute(k_gru_fused, cudaFuncAttributeMaxDynamicSharedMemorySize, FUSED_SMEM);
        attr_set = true;
    }

    // weight splits + decoder-input cast
    k_split_w<<<(Gd * Hd) / 256, 256>>>(enc_whh, WHHE2);
    k_split_w<<<(Gd * Hd) / 256, 256>>>(dec_whh, WHHD2);
    k_split_w<<<(Gd * Hd) / 256, 256>>>(dec_wih, WIHD2);
    k_split_w<<<(Hd * Hd) / 256, 256>>>(w3, W32);
    k_split_w<<<(Hd * Hd) / 256, 256>>>(w4, W42);
    k_cast<<<(Bz * Hd) / 256, 256>>>(dec_in, DEC1);

    // combined encoder input weights
    k_combine<<<Gd, 128>>>(enc_wih, emb_w, emb_b, enc_bih, CW, CB);

    // decoder input gates (step-invariant)
    k_gemm_mma<<<dim3(Bz / 128, Gd / 128), 256>>>(DEC1, WIHD2, dec_bih, XG_DEC, Gd);

    // encoder scan
    k_gate_enc0<<<(Bz * Hd) / 256, 256>>>(items, CW, CB, enc_bhh, ENC_OUT, ENC1);
    for (int t = 1; t < Ls; t++) {
        k_gru_fused<<<dim3(Bz / 128, Hd / 128), 256, FUSED_SMEM>>>(
            ENC1 + (size_t)(t - 1) * Bz * Hd, WHHE2, enc_bhh,
            nullptr, items, t, CW, CB,
            ENC_OUT + (size_t)(t - 1) * Bz * Hd,
            ENC_OUT + (size_t)t * Bz * Hd,
            ENC1 + (size_t)t * Bz * Hd);
    }

    // enc_w3 = enc_out @ w3^T  (all Ls*Bz rows batched)
    k_gemm_mma<<<dim3((Ls * Bz) / 128, Hd / 128), 256>>>(ENC1, W32, nullptr, ENC_W3, Hd);

    // decoder scan (fused GRU steps; w4 GEMM batched after)
    const float*  hp  = ENC_OUT + (size_t)(Ls - 1) * Bz * Hd;
    const __half* hp1 = ENC1    + (size_t)(Ls - 1) * Bz * Hd;
    for (int t = 0; t < Ls; t++) {
        float*  ht  = H_ALL  + (size_t)t * Bz * Hd;
        __half* ht1 = H1_ALL + (size_t)t * Bz * Hd;
        k_gru_fused<<<dim3(Bz / 128, Hd / 128), 256, FUSED_SMEM>>>(
            hp1, WHHD2, dec_bhh,
            XG_DEC, nullptr, 0, nullptr, nullptr,
            hp, ht, ht1);
        hp = ht; hp1 = ht1;
    }

    // A_ALL = H1_ALL @ w4^T  (all Ls*Bz rows batched)
    k_gemm_mma<<<dim3((Ls * Bz) / 128, Hd / 128), 256>>>(H1_ALL, W42, nullptr, A_ALL, Hd);

    // batched epilogues
    k_seq_all<<<Bz, 256>>>(ENC_W3, A_ALL, v2, out_seq);
    k_ori_all<<<(Bz * Ls) / 8, 256>>>(H_ALL, wori, bori, out_ori);
}

// round 9
// speedup vs baseline: 1.5909x; 1.5909x over previous
#include <cuda_runtime.h>
#include <cuda_fp16.h>
#include <cstdint>
#include <math.h>

static constexpr int Bz  = 4096;
static constexpr int Ls  = 10;
static constexpr int IND = 8;
static constexpr int Hd  = 512;
static constexpr int Gd  = 1536;   // 3*Hd

// ---------------- scratch (offsets in float units) ----------------
static constexpr size_t OFF_XG_DEC  = 0;                                     // Bz*Gd f32
static constexpr size_t OFF_HG      = OFF_XG_DEC  + (size_t)Bz*Gd;           // Bz*Gd f32
static constexpr size_t OFF_ENC_OUT = OFF_HG      + (size_t)Bz*Gd;           // Ls*Bz*Hd f32
static constexpr size_t OFF_ENC1    = OFF_ENC_OUT + (size_t)Ls*Bz*Hd;        // Ls*Bz*Hd fp16
static constexpr size_t OFF_ENC_W3  = OFF_ENC1    + (size_t)Ls*Bz*Hd/2;      // Ls*Bz*Hd f32
static constexpr size_t OFF_H_ALL   = OFF_ENC_W3  + (size_t)Ls*Bz*Hd;        // Ls*Bz*Hd f32
static constexpr size_t OFF_A_ALL   = OFF_H_ALL   + (size_t)Ls*Bz*Hd;        // Ls*Bz*Hd f32
static constexpr size_t OFF_H1_ALL  = OFF_A_ALL   + (size_t)Ls*Bz*Hd;        // Ls*Bz*Hd fp16
static constexpr size_t OFF_DEC1    = OFF_H1_ALL  + (size_t)Ls*Bz*Hd/2;      // Bz*Hd fp16
static constexpr size_t OFF_WHHE1   = OFF_DEC1    + (size_t)Bz*Hd/2;         // Gd*Hd fp16
static constexpr size_t OFF_WHHD1   = OFF_WHHE1   + (size_t)Gd*Hd/2;
static constexpr size_t OFF_WIHD1   = OFF_WHHD1   + (size_t)Gd*Hd/2;
static constexpr size_t OFF_W31     = OFF_WIHD1   + (size_t)Gd*Hd/2;         // Hd*Hd fp16
static constexpr size_t OFF_W41     = OFF_W31     + (size_t)Hd*Hd/2;
static constexpr size_t OFF_CW      = OFF_W41     + (size_t)Hd*Hd/2;         // Gd*IND f32
static constexpr size_t OFF_CB      = OFF_CW      + (size_t)Gd*IND;          // Gd f32
static constexpr size_t SCRATCH_TOTAL = OFF_CB + Gd;

__device__ __align__(1024) float g_scratch[SCRATCH_TOTAL];

// ---------------- math helpers ----------------
__device__ __forceinline__ float sigm_f(float x) { return 1.0f / (1.0f + __expf(-x)); }
__device__ __forceinline__ float tanh_f(float x) {
    float ax = fabsf(x);
    float t  = __expf(-2.0f * ax);
    float r  = __fdividef(1.0f - t, 1.0f + t);
    return copysignf(r, x);
}

// ---------------- PTX helpers ----------------
__device__ __forceinline__ uint32_t smem_u32(const void* p) {
    uint32_t a;
    asm("{ .reg .u64 t; cvta.to.shared.u64 t, %1; cvt.u32.u64 %0, t; }" : "=r"(a) : "l"(p));
    return a;
}
__device__ __forceinline__ void cp16(uint32_t s, const void* g) {
    asm volatile("cp.async.cg.shared.global [%0], [%1], 16;" :: "r"(s), "l"(g) : "memory");
}
__device__ __forceinline__ void ldm_x4(uint32_t& r0, uint32_t& r1, uint32_t& r2, uint32_t& r3,
                                       uint32_t addr) {
    asm volatile("ldmatrix.sync.aligned.m8n8.x4.shared.b16 {%0,%1,%2,%3}, [%4];"
                 : "=r"(r0), "=r"(r1), "=r"(r2), "=r"(r3) : "r"(addr));
}
__device__ __forceinline__ void mma16816(float* c, const uint32_t* a, uint32_t b0, uint32_t b1) {
    asm volatile("mma.sync.aligned.m16n8k16.row.col.f32.f16.f16.f32 "
                 "{%0,%1,%2,%3}, {%4,%5,%6,%7}, {%8,%9}, {%0,%1,%2,%3};"
                 : "+f"(c[0]), "+f"(c[1]), "+f"(c[2]), "+f"(c[3])
                 : "r"(a[0]), "r"(a[1]), "r"(a[2]), "r"(a[3]), "r"(b0), "r"(b1));
}

static constexpr int AB_STRIDE = 10240;   // 128 rows * 80 B

// ---------------- fp16 tensor-core GEMM: C[M,N] = A @ W^T (+bias) ----------------
// A1[M,512], W1[N,512] fp16. 16 K-tiles of 32, 2-stage cp.async double buffer.
// 128x128 CTA tile, 256 threads (8 warps of 32x64). 80-byte smem rows (conflict-free).
__global__ void __launch_bounds__(256, 2) k_gemm_mma(
    const __half* __restrict__ A1, const __half* __restrict__ W1,
    const float* __restrict__ bias, float* __restrict__ C, int N)
{
    __shared__ __half As[2][128][40];
    __shared__ __half Bs[2][128][40];
    const int tid  = threadIdx.x;
    const int wid  = tid >> 5, lane = tid & 31;
    const int wm   = wid & 3;
    const int wn   = wid >> 2;
    const size_t bm = (size_t)blockIdx.x * 128;
    const size_t bn = (size_t)blockIdx.y * 128;

    const uint32_t sA = smem_u32(As);
    const uint32_t sB = smem_u32(Bs);

    float acc[2][8][4];
#pragma unroll
    for (int i = 0; i < 2; i++)
#pragma unroll
        for (int j = 0; j < 8; j++)
#pragma unroll
            for (int q = 0; q < 4; q++) acc[i][j][q] = 0.0f;

    const int lrow = tid >> 2;             // 0..63
    const int lcol = (tid & 3) << 4;       // byte 0,16,32,48
    const char* aG = (const char*)A1 + (bm + lrow) * 1024 + lcol;
    const char* bG = (const char*)W1 + (bn + lrow) * 1024 + lcol;
    const uint32_t dA = sA + lrow * 80 + lcol;
    const uint32_t dB = sB + lrow * 80 + lcol;

#define LOAD_TILE(kt, buf)                                                \
    {                                                                     \
        int ko_ = (kt) * 64;                                              \
        cp16(dA + (buf) * AB_STRIDE,           aG + ko_);                 \
        cp16(dA + (buf) * AB_STRIDE + 64 * 80, aG + 64 * 1024 + ko_);     \
        cp16(dB + (buf) * AB_STRIDE,           bG + ko_);                 \
        cp16(dB + (buf) * AB_STRIDE + 64 * 80, bG + 64 * 1024 + ko_);     \
        asm volatile("cp.async.commit_group;" ::: "memory");              \
    }

    LOAD_TILE(0, 0);

    const uint32_t mA0 = sA + (wm * 32 + (lane & 15)) * 80 + ((lane >> 4) << 4);
    const uint32_t mB0 = sB + (wn * 64 + (lane & 15)) * 80 + ((lane >> 4) << 4);

    for (int kt = 0; kt < 16; kt++) {
        int buf = kt & 1;
        if (kt < 15) {
            LOAD_TILE(kt + 1, buf ^ 1);
            asm volatile("cp.async.wait_group 1;" ::: "memory");
        } else {
            asm volatile("cp.async.wait_group 0;" ::: "memory");
        }
        __syncthreads();

#pragma unroll
        for (int ks = 0; ks < 2; ks++) {
            uint32_t a[2][4], b[4][4];
#pragma unroll
            for (int mf = 0; mf < 2; mf++)
                ldm_x4(a[mf][0], a[mf][1], a[mf][2], a[mf][3],
                       mA0 + buf * AB_STRIDE + mf * 16 * 80 + ks * 32);
#pragma unroll
            for (int nb = 0; nb < 4; nb++)
                ldm_x4(b[nb][0], b[nb][1], b[nb][2], b[nb][3],
                       mB0 + buf * AB_STRIDE + nb * 16 * 80 + ks * 32);
#pragma unroll
            for (int mf = 0; mf < 2; mf++)
#pragma unroll
                for (int nb = 0; nb < 4; nb++) {
                    mma16816(acc[mf][2 * nb + 0], a[mf], b[nb][0], b[nb][2]);
                    mma16816(acc[mf][2 * nb + 1], a[mf], b[nb][1], b[nb][3]);
                }
        }
        __syncthreads();
    }
#undef LOAD_TILE

#pragma unroll
    for (int mf = 0; mf < 2; mf++) {
#pragma unroll
        for (int nf = 0; nf < 8; nf++) {
            size_t r0 = bm + wm * 32 + mf * 16 + (lane >> 2);
            int    c0 = (int)bn + wn * 64 + nf * 8 + (lane & 3) * 2;
            float bv0 = 0.f, bv1 = 0.f;
            if (bias) { bv0 = bias[c0]; bv1 = bias[c0 + 1]; }
            float2 o0 = make_float2(acc[mf][nf][0] + bv0, acc[mf][nf][1] + bv1);
            float2 o1 = make_float2(acc[mf][nf][2] + bv0, acc[mf][nf][3] + bv1);
            *reinterpret_cast<float2*>(&C[r0 * (size_t)N + c0])       = o0;
            *reinterpret_cast<float2*>(&C[(r0 + 8) * (size_t)N + c0]) = o1;
        }
    }
}

// ---------------- cast: f32 -> fp16 ----------------
__global__ void k_cast(const float* __restrict__ in, __half* __restrict__ out)
{
    size_t idx = (size_t)blockIdx.x * blockDim.x + threadIdx.x;
    out[idx] = __float2half(in[idx]);
}

// ---------------- combine: cw = enc_wih @ emb_w, cb = enc_wih@emb_b + enc_bih ----------------
__global__ void k_combine(const float* __restrict__ enc_wih, const float* __restrict__ emb_w,
                          const float* __restrict__ emb_b,  const float* __restrict__ enc_bih,
                          float* __restrict__ cw, float* __restrict__ cb)
{
    int g = blockIdx.x, tid = threadIdx.x;
    float p[IND + 1];
#pragma unroll
    for (int i = 0; i <= IND; i++) p[i] = 0.0f;
    const float* wr = enc_wih + (size_t)g * Hd;
    for (int k = tid; k < Hd; k += 128) {
        float wv = wr[k];
#pragma unroll
        for (int i = 0; i < IND; i++) p[i] += wv * emb_w[(size_t)k * IND + i];
        p[IND] += wv * emb_b[k];
    }
#pragma unroll
    for (int i = 0; i <= IND; i++)
        for (int o = 16; o; o >>= 1) p[i] += __shfl_xor_sync(0xffffffffu, p[i], o);
    __shared__ float red[IND + 1][4];
    int wid = tid >> 5, lane = tid & 31;
    if (!lane)
#pragma unroll
        for (int i = 0; i <= IND; i++) red[i][wid] = p[i];
    __syncthreads();
    if (tid <= IND) {
        float s = red[tid][0] + red[tid][1] + red[tid][2] + red[tid][3];
        if (tid < IND) cw[(size_t)g * IND + tid] = s;
        else           cb[g] = s + enc_bih[g];
    }
}

// ---------------- encoder GRU gate with inline input-gate dot ----------------
__global__ void k_gate_enc(const float* __restrict__ items, int t,
                           const float* __restrict__ cw, const float* __restrict__ cb,
                           const float* __restrict__ hg, const float* __restrict__ bhh,
                           const float* __restrict__ hprev,
                           float* __restrict__ hout, __half* __restrict__ h1)
{
    int idx = blockIdx.x * blockDim.x + threadIdx.x;
    int b = idx >> 9, j = idx & 511;
    const float4* it = reinterpret_cast<const float4*>(items + ((size_t)b * Ls + t) * IND);
    float4 i0 = it[0], i1 = it[1];
    auto xdot = [&](int g) {
        const float4* w = reinterpret_cast<const float4*>(cw + (size_t)g * IND);
        float4 w0 = w[0], w1 = w[1];
        return cb[g]
            + i0.x * w0.x + i0.y * w0.y + i0.z * w0.z + i0.w * w0.w
            + i1.x * w1.x + i1.y * w1.y + i1.z * w1.z + i1.w * w1.w;
    };
    float xr = xdot(j), xz = xdot(Hd + j), xn = xdot(2 * Hd + j);

    float hr, hz, hn;
    if (hg) {
        const float* hrow = hg + (size_t)b * Gd;
        hr = hrow[j]; hz = hrow[Hd + j]; hn = hrow[2 * Hd + j];
    } else {
        hr = bhh[j]; hz = bhh[Hd + j]; hn = bhh[2 * Hd + j];
    }
    float hp = hprev ? hprev[idx] : 0.0f;
    float r = sigm_f(xr + hr);
    float z = sigm_f(xz + hz);
    float n = tanh_f(xn + r * hn);
    float v = n + z * (hp - n);
    hout[idx] = v;
    h1[idx] = __float2half(v);
}

// ---------------- decoder GRU gate ----------------
__global__ void k_gate_dec(const float* __restrict__ xg, const float* __restrict__ hg,
                           const float* __restrict__ hprev,
                           float* __restrict__ hout, __half* __restrict__ h1)
{
    int idx = blockIdx.x * blockDim.x + threadIdx.x;
    int b = idx >> 9, j = idx & 511;
    const float* xrow = xg + (size_t)b * Gd;
    const float* hrow = hg + (size_t)b * Gd;
    float r = sigm_f(xrow[j] + hrow[j]);
    float z = sigm_f(xrow[Hd + j] + hrow[Hd + j]);
    float n = tanh_f(xrow[2 * Hd + j] + r * hrow[2 * Hd + j]);
    float hp = hprev[idx];
    float v = n + z * (hp - n);
    hout[idx] = v;
    h1[idx] = __float2half(v);
}

// ---------------- batched out_seq over all (t, l): one block per b ----------------
__global__ void __launch_bounds__(256) k_seq_all(
    const float* __restrict__ encw3, const float* __restrict__ A_all,
    const float* __restrict__ v2, float* __restrict__ out)
{
    int b = blockIdx.x, tid = threadIdx.x;
    int wid = tid >> 5, lane = tid & 31;
    __shared__ float Ash[Ls][Hd];
    __shared__ float v2s[Hd];
    __shared__ float red[8][Ls];
    for (int i = tid; i < Hd; i += 256) v2s[i] = v2[i];
    for (int t = 0; t < Ls; t++)
        for (int i = tid; i < Hd; i += 256)
            Ash[t][i] = A_all[((size_t)t * Bz + b) * Hd + i];
    __syncthreads();

    for (int l = 0; l < Ls; l++) {
        const float* e = encw3 + ((size_t)l * Bz + b) * Hd;
        float s[Ls];
#pragma unroll
        for (int t = 0; t < Ls; t++) s[t] = 0.0f;
#pragma unroll
        for (int it = 0; it < 2; it++) {
            int k = tid + it * 256;
            float ek = e[k], vk = v2s[k];
#pragma unroll
            for (int t = 0; t < Ls; t++) s[t] += vk * tanh_f(ek + Ash[t][k]);
        }
#pragma unroll
        for (int t = 0; t < Ls; t++)
            for (int o = 16; o; o >>= 1) s[t] += __shfl_xor_sync(0xffffffffu, s[t], o);
        if (!lane)
#pragma unroll
            for (int t = 0; t < Ls; t++) red[wid][t] = s[t];
        __syncthreads();
        if (tid < Ls) {
            float tot = 0.0f;
#pragma unroll
            for (int w = 0; w < 8; w++) tot += red[w][tid];
            out[((size_t)b * Ls + tid) * Ls + l] = tot;
        }
        __syncthreads();
    }
}

// ---------------- batched out_ori: one warp per (t, b) ----------------
__global__ void k_ori_all(const float* __restrict__ H_all, const float* __restrict__ wori,
                          const float* __restrict__ bori, float* __restrict__ out)
{
    int gw   = (blockIdx.x * blockDim.x + threadIdx.x) >> 5;  // t*Bz + b
    int lane = threadIdx.x & 31;
    int t = gw >> 12, b = gw & 4095;
    float s[6] = {0, 0, 0, 0, 0, 0};
    const float* hb = H_all + ((size_t)t * Bz + b) * Hd;
    for (int k = lane; k < Hd; k += 32) {
        float hv = hb[k];
#pragma unroll
        for (int j = 0; j < 6; j++) s[j] += hv * wori[(size_t)j * Gd + Hd + k];
    }
#pragma unroll
    for (int j = 0; j < 6; j++)
        for (int o = 16; o; o >>= 1) s[j] += __shfl_xor_sync(0xffffffffu, s[j], o);
    if (!lane)
#pragma unroll
        for (int j = 0; j < 6; j++)
            out[((size_t)b * Ls + t) * 6 + j] = s[j] + bori[j];
}

// ---------------- launch ----------------
extern "C" void kernel_launch(void* const* d_in, const int* in_sizes, int n_in,
                              void* d_out, int out_size)
{
    const float* items    = (const float*)d_in[0];
    const float* dec_in   = (const float*)d_in[1];
    const float* emb_w    = (const float*)d_in[2];
    const float* emb_b    = (const float*)d_in[3];
    const float* enc_wih  = (const float*)d_in[4];
    const float* enc_whh  = (const float*)d_in[5];
    const float* enc_bih  = (const float*)d_in[6];
    const float* enc_bhh  = (const float*)d_in[7];
    const float* dec_wih  = (const float*)d_in[8];
    const float* dec_whh  = (const float*)d_in[9];
    const float* dec_bih  = (const float*)d_in[10];
    const float* dec_bhh  = (const float*)d_in[11];
    const float* w3       = (const float*)d_in[14];
    const float* w4       = (const float*)d_in[15];
    const float* v2       = (const float*)d_in[20];
    const float* wori     = (const float*)d_in[23];
    const float* bori     = (const float*)d_in[24];

    float* out_seq = (float*)d_out;                        // (Bz, Ls, Ls)
    float* out_ori = (float*)d_out + (size_t)Bz * Ls * Ls; // (Bz, Ls, 6)

    float* S = nullptr;
    cudaGetSymbolAddress((void**)&S, g_scratch);
    float* XG_DEC  = S + OFF_XG_DEC;
    float* HG      = S + OFF_HG;
    float* ENC_OUT = S + OFF_ENC_OUT;
    float* ENC_W3  = S + OFF_ENC_W3;
    float* H_ALL   = S + OFF_H_ALL;
    float* A_ALL   = S + OFF_A_ALL;
    float* CW      = S + OFF_CW;
    float* CB      = S + OFF_CB;
    __half* ENC1   = (__half*)(S + OFF_ENC1);
    __half* H1_ALL = (__half*)(S + OFF_H1_ALL);
    __half* DEC1   = (__half*)(S + OFF_DEC1);
    __half* WHHE1  = (__half*)(S + OFF_WHHE1);
    __half* WHHD1  = (__half*)(S + OFF_WHHD1);
    __half* WIHD1  = (__half*)(S + OFF_WIHD1);
    __half* W31    = (__half*)(S + OFF_W31);
    __half* W41    = (__half*)(S + OFF_W41);

    // weight casts + decoder-input cast
    k_cast<<<(Gd * Hd) / 256, 256>>>(enc_whh, WHHE1);
    k_cast<<<(Gd * Hd) / 256, 256>>>(dec_whh, WHHD1);
    k_cast<<<(Gd * Hd) / 256, 256>>>(dec_wih, WIHD1);
    k_cast<<<(Hd * Hd) / 256, 256>>>(w3, W31);
    k_cast<<<(Hd * Hd) / 256, 256>>>(w4, W41);
    k_cast<<<(Bz * Hd) / 256, 256>>>(dec_in, DEC1);

    // combined encoder input weights
    k_combine<<<Gd, 128>>>(enc_wih, emb_w, emb_b, enc_bih, CW, CB);

    // decoder input gates (step-invariant)
    k_gemm_mma<<<dim3(Bz / 128, Gd / 128), 256>>>(DEC1, WIHD1, dec_bih, XG_DEC, Gd);

    // encoder GRU scan
    for (int t = 0; t < Ls; t++) {
        const float* hp = t ? (ENC_OUT + (size_t)(t - 1) * Bz * Hd) : nullptr;
        if (t)
            k_gemm_mma<<<dim3(Bz / 128, Gd / 128), 256>>>(
                ENC1 + (size_t)(t - 1) * Bz * Hd, WHHE1, enc_bhh, HG, Gd);
        k_gate_enc<<<(Bz * Hd) / 256, 256>>>(items, t, CW, CB,
                                             t ? HG : nullptr, enc_bhh, hp,
                                             ENC_OUT + (size_t)t * Bz * Hd,
                                             ENC1 + (size_t)t * Bz * Hd);
    }

    // enc_w3 = enc_out @ w3^T  (all Ls*Bz rows batched)
    k_gemm_mma<<<dim3((Ls * Bz) / 128, Hd / 128), 256>>>(ENC1, W31, nullptr, ENC_W3, Hd);

    // decoder scan (w4 GEMM batched after)
    const float*  hp  = ENC_OUT + (size_t)(Ls - 1) * Bz * Hd;
    const __half* hp1 = ENC1    + (size_t)(Ls - 1) * Bz * Hd;
    for (int t = 0; t < Ls; t++) {
        float*  ht  = H_ALL  + (size_t)t * Bz * Hd;
        __half* ht1 = H1_ALL + (size_t)t * Bz * Hd;
        k_gemm_mma<<<dim3(Bz / 128, Gd / 128), 256>>>(hp1, WHHD1, dec_bhh, HG, Gd);
        k_gate_dec<<<(Bz * Hd) / 256, 256>>>(XG_DEC, HG, hp, ht, ht1);
        hp = ht; hp1 = ht1;
    }

    // A_ALL = H1_ALL @ w4^T  (all Ls*Bz rows batched)
    k_gemm_mma<<<dim3((Ls * Bz) / 128, Hd / 128), 256>>>(H1_ALL, W41, nullptr, A_ALL, Hd);

    // batched epilogues
    k_seq_all<<<Bz, 256>>>(ENC_W3, A_ALL, v2, out_seq);
    k_ori_all<<<(Bz * Ls) / 8, 256>>>(H_ALL, wori, bori, out_ori);
}